// round 8
// baseline (speedup 1.0000x reference)
#include <cuda_runtime.h>
#include <math.h>

// Problem constants
#define H    2048
#define E    8
#define I16  16
#define NTOK 8192
#define NB   64            // bucket ids lo*8+hi (28 valid)
#define TB   64            // tokens per tile
#define KC   64            // k-chunk (phase A)
#define NCH  (H / KC)      // 32
#define XP   68            // X/D row pitch (floats), mod 32 = 4
#define ASP  68            // Red/As pitch over tokens
#define UP   516           // Us row pitch (floats)

// smem layout (float offsets); Us (phase B) reuses the Red region
#define XDSZ     (96 * XP)                  // one X+D buffer: 6528 floats
#define RED_OFF  (2 * XDSZ)                 // 13056
#define AS_OFF   (RED_OFF + 16 * 32 * ASP)  // 13056 + 34816 = 47872
#define SM_FLOATS (AS_OFF + 32 * ASP)       // 50048 floats = 200192 B

// f32x2 packed-math helpers
#define FMA2(d, a, b) asm("fma.rn.f32x2 %0, %1, %2, %0;" : "+l"(d) : "l"(a), "l"(b))
#define PACK2(d, f)   asm("mov.b64 %0, {%1, %1};" : "=l"(d) : "f"(f))
#define UNPACK2(lo, hi, d) asm("mov.b64 {%0, %1}, %2;" : "=f"(lo), "=f"(hi) : "l"(d))

__device__ __forceinline__ unsigned su32(const void* p) {
    return (unsigned)__cvta_generic_to_shared(p);
}
#define CP16(dst, src) asm volatile("cp.async.cg.shared.global [%0], [%1], 16;" :: "r"(dst), "l"(src))
#define CP_COMMIT()    asm volatile("cp.async.commit_group;" ::: "memory")
#define CP_WAIT1()     asm volatile("cp.async.wait_group 1;" ::: "memory")
#define CP_WAIT0()     asm volatile("cp.async.wait_group 0;" ::: "memory")

// ---------------- device scratch ----------------
__device__ int    g_count[NB];
__device__ int    g_tok[NB][NTOK];
__device__ float2 g_gate[NB][NTOK];

// ---------------- K1: router (no smem; rw is L1-resident; 4 tok/warp) ----
__global__ __launch_bounds__(256)
void router_kernel(const float* __restrict__ x,
                   const float* __restrict__ rw) {
    const int w = threadIdx.x >> 5;
    const int l = threadIdx.x & 31;
    const int t0 = blockIdx.x * 32 + w * 4;

    unsigned long long acc[E][4];
#pragma unroll
    for (int e = 0; e < E; e++)
#pragma unroll
        for (int j = 0; j < 4; j++) acc[e][j] = 0ull;

    for (int s = 0; s < 16; s++) {
        ulonglong2 xv[4];
#pragma unroll
        for (int j = 0; j < 4; j++)
            xv[j] = ((const ulonglong2*)(x + (size_t)(t0 + j) * H))[l + 32 * s];
#pragma unroll
        for (int e = 0; e < E; e++) {
            ulonglong2 wv = ((const ulonglong2*)(rw + e * H))[l + 32 * s];
#pragma unroll
            for (int j = 0; j < 4; j++) {
                FMA2(acc[e][j], xv[j].x, wv.x);
                FMA2(acc[e][j], xv[j].y, wv.y);
            }
        }
    }

    float lg[E];
#pragma unroll
    for (int e = 0; e < E; e++) {
#pragma unroll
        for (int j = 0; j < 4; j++) {
            float s0, s1;
            UNPACK2(s0, s1, acc[e][j]);
            float v = s0 + s1;
#pragma unroll
            for (int o = 16; o > 0; o >>= 1) v += __shfl_xor_sync(0xffffffffu, v, o);
            if (l == j) lg[e] = v;
        }
    }

    if (l < 4) {
        int t = t0 + l;
        float m = lg[0];
#pragma unroll
        for (int e = 1; e < E; e++) m = fmaxf(m, lg[e]);
        float wgt[E]; float ssum = 0.f;
#pragma unroll
        for (int e = 0; e < E; e++) { wgt[e] = __expf(lg[e] - m); ssum += wgt[e]; }
        float inv = 1.f / ssum;

        int i1 = 0; float v1 = wgt[0];
#pragma unroll
        for (int e = 1; e < E; e++) if (wgt[e] > v1) { v1 = wgt[e]; i1 = e; }
        int i2 = -1; float v2 = -1.f;
#pragma unroll
        for (int e = 0; e < E; e++)
            if (e != i1 && wgt[e] > v2) { v2 = wgt[e]; i2 = e; }

        float g1 = v1 * inv, g2 = v2 * inv;
        int lo, hi; float glo, ghi;
        if (i1 < i2) { lo = i1; hi = i2; glo = g1; ghi = g2; }
        else         { lo = i2; hi = i1; glo = g2; ghi = g1; }
        int p = lo * 8 + hi;
        int slot = atomicAdd(&g_count[p], 1);
        g_tok[p][slot]  = t;
        g_gate[p][slot] = make_float2(glo, ghi);
    }
}

// ---------------- K2: expert compute, 512 threads / 16 warps ----------------
// Phase A: C[64 tok][32 i] = X·D^T, split-K x16 (warp = 4-k slice of KC=64
//   chunk), thread tile 8 tok x 8 i; cp.async double-buffered.
// Phase B: out = A·U. warp = (token-group 0..7) x (h-half 0..1),
//   thread tile 8 tok x 8 h. Us[32][512] staged in the Red region.
__global__ __launch_bounds__(512, 1)
void expert_kernel(const float* __restrict__ x,
                   const float* __restrict__ dw,
                   const float* __restrict__ uw,
                   float* __restrict__ out) {
    extern __shared__ float sm[];
    float* Red = sm + RED_OFF;
    float* As  = sm + AS_OFF;
    float* Us  = sm + RED_OFF;       // Us reuses Red region in phase B

    __shared__ int    pref[NB + 1];
    __shared__ int    Ts[TB];
    __shared__ float2 Gs[TB];

    const int tid = threadIdx.x;
    const int w = tid >> 5;          // 0..15: k-slice (A) / tok-group+h-half (B)
    const int l = tid & 31;
    // phase A lane ids
    const int tg = l & 7;            // token interleave
    const int ig = l >> 3;           // i interleave 0..3
    // phase B warp ids
    const int wt = w & 7;            // token group
    const int wh = w >> 3;           // h half

    // flat tile prefix over buckets
    if (tid < NB) {
        int lo_ = tid >> 3, hi_ = tid & 7;
        pref[tid + 1] = (lo_ < hi_) ? (g_count[tid] + TB - 1) / TB : 0;
    }
    __syncthreads();
    if (tid == 0) {
        int s = 0;
        pref[0] = 0;
        for (int i = 1; i <= NB; i++) { s += pref[i]; pref[i] = s; }
    }
    __syncthreads();
    const int ntiles = pref[NB];

    for (int ft = blockIdx.x; ft < ntiles; ft += gridDim.x) {
        int a = 0, b = NB;
        while (b - a > 1) { int mM = (a + b) >> 1; if (pref[mM] <= ft) a = mM; else b = mM; }
        const int p  = a;
        const int lo = p >> 3, hi = p & 7;
        const int cnt  = g_count[p];
        const int base = (ft - pref[p]) * TB;
        const int n    = min(TB, cnt - base);

        __syncthreads();             // prev tile fully done with smem
        if (tid < TB) {
            int src = base + ((tid < n) ? tid : 0);
            Ts[tid] = g_tok[p][src];
            float2 gg = g_gate[p][src];
            if (tid >= n) gg = make_float2(0.f, 0.f);
            Gs[tid] = gg;
        }
        __syncthreads();

        // ================= Phase A =================
        unsigned long long accP[8][8];
#pragma unroll
        for (int u = 0; u < 8; u++)
#pragma unroll
            for (int v = 0; v < 8; v++) accP[u][v] = 0ull;

        auto stage = [&](int c, int bb) {
            float* dst = sm + bb * XDSZ;
            int koff = c * KC;
#pragma unroll
            for (int j = 0; j < 2; j++) {
                int idx = tid + 512 * j, r = idx >> 4, q = idx & 15;
                CP16(su32(dst + r * XP + 4 * q),
                     x + (size_t)Ts[r] * H + koff + 4 * q);
            }
            {
                int r = tid >> 4, q = tid & 15;
                int e = (r < 16) ? lo : hi;
                CP16(su32(dst + (64 + r) * XP + 4 * q),
                     dw + (size_t)(e * I16 + (r & 15)) * H + koff + 4 * q);
            }
        };

        stage(0, 0); CP_COMMIT();
        stage(1, 1); CP_COMMIT();

        for (int c = 0; c < NCH; c++) {
            if (c == NCH - 1) { CP_WAIT0(); } else { CP_WAIT1(); }
            __syncthreads();
            const ulonglong2* B4 = (const ulonglong2*)(sm + (c & 1) * XDSZ);

            ulonglong2 xv[8];
#pragma unroll
            for (int u = 0; u < 8; u++)
                xv[u] = B4[(tg + 8 * u) * 17 + w];
#pragma unroll
            for (int v = 0; v < 8; v++) {
                ulonglong2 dv = B4[(64 + ig + 4 * v) * 17 + w];
#pragma unroll
                for (int u = 0; u < 8; u++) {
                    FMA2(accP[u][v], xv[u].x, dv.x);
                    FMA2(accP[u][v], xv[u].y, dv.y);
                }
            }
            __syncthreads();
            if (c + 2 < NCH) { stage(c + 2, c & 1); CP_COMMIT(); }
        }

        // split-K partials -> Red[w][i][t]
#pragma unroll
        for (int u = 0; u < 8; u++)
#pragma unroll
            for (int v = 0; v < 8; v++) {
                float s0, s1;
                UNPACK2(s0, s1, accP[u][v]);
                Red[w * (32 * ASP) + (ig + 4 * v) * ASP + (tg + 8 * u)] = s0 + s1;
            }
        __syncthreads();

        // reduce(16) + silu + gate -> As[i][t]
#pragma unroll
        for (int j = 0; j < 4; j++) {
            int idx = j * 512 + tid;
            int i = idx >> 6, t = idx & 63;
            float hv = 0.f;
#pragma unroll
            for (int kk = 0; kk < 16; kk++)
                hv += Red[kk * (32 * ASP) + i * ASP + t];
            float2 gg = Gs[t];
            float gate = (i < 16) ? gg.x : gg.y;
            float sig = 1.f / (1.f + __expf(-hv));
            As[i * ASP + t] = gate * hv * sig;
        }
        __syncthreads();             // As ready; Red region free for Us

        // ================= Phase B =================
        for (int pass = 0; pass < 4; pass++) {
            // stage Us[32 i][512 h] into Red region
            float4 ub[8];
#pragma unroll
            for (int j = 0; j < 8; j++) {
                int idx = j * 512 + tid;
                int eiq = idx >> 9, h = idx & 511;
                int e2 = eiq >> 2, iq = eiq & 3;
                int eg = e2 ? hi : lo;
                ub[j] = *(const float4*)(uw + ((size_t)eg * H + pass * 512 + h) * I16 + 4 * iq);
            }
#pragma unroll
            for (int j = 0; j < 8; j++) {
                int idx = j * 512 + tid;
                int eiq = idx >> 9, h = idx & 511;
                int e2 = eiq >> 2, iq = eiq & 3;
                int rb = e2 * 16 + 4 * iq;
                Us[(rb + 0) * UP + h] = ub[j].x;
                Us[(rb + 1) * UP + h] = ub[j].y;
                Us[(rb + 2) * UP + h] = ub[j].z;
                Us[(rb + 3) * UP + h] = ub[j].w;
            }
            __syncthreads();

            ulonglong2 acc2[8][2];   // [token j][h float4 m]
#pragma unroll
            for (int j = 0; j < 8; j++)
#pragma unroll
                for (int m = 0; m < 2; m++) { acc2[j][m].x = 0ull; acc2[j][m].y = 0ull; }

#pragma unroll 4
            for (int k = 0; k < 32; k++) {
                float4 aA = *(const float4*)(As + k * ASP + wt * 8);
                float4 aB = *(const float4*)(As + k * ASP + wt * 8 + 4);
                unsigned long long ap[8];
                PACK2(ap[0], aA.x); PACK2(ap[1], aA.y);
                PACK2(ap[2], aA.z); PACK2(ap[3], aA.w);
                PACK2(ap[4], aB.x); PACK2(ap[5], aB.y);
                PACK2(ap[6], aB.z); PACK2(ap[7], aB.w);
#pragma unroll
                for (int m = 0; m < 2; m++) {
                    ulonglong2 uv = *(const ulonglong2*)(Us + k * UP + wh * 256 + 4 * l + 128 * m);
#pragma unroll
                    for (int j = 0; j < 8; j++) {
                        FMA2(acc2[j][m].x, ap[j], uv.x);
                        FMA2(acc2[j][m].y, ap[j], uv.y);
                    }
                }
            }

#pragma unroll
            for (int j = 0; j < 8; j++) {
                int tl = wt * 8 + j;
                if (tl < n) {
                    float* orow = out + (size_t)Ts[tl] * H + pass * 512 + wh * 256 + 4 * l;
#pragma unroll
                    for (int m = 0; m < 2; m++) {
                        float4 ov;
                        UNPACK2(ov.x, ov.y, acc2[j][m].x);
                        UNPACK2(ov.z, ov.w, acc2[j][m].y);
                        *(float4*)(orow + 128 * m) = ov;
                    }
                }
            }
            __syncthreads();         // before next pass overwrites Us
        }
    }
}

// ---------------- launch ----------------
extern "C" void kernel_launch(void* const* d_in, const int* in_sizes, int n_in,
                              void* d_out, int out_size) {
    const float* x  = (const float*)d_in[0];
    const float* rw = (const float*)d_in[1];
    const float* dw = (const float*)d_in[2];
    const float* uw = (const float*)d_in[3];
    float* out = (float*)d_out;

    const int ek_smem = SM_FLOATS * sizeof(float); // 200192 B
    cudaFuncSetAttribute(expert_kernel, cudaFuncAttributeMaxDynamicSharedMemorySize, ek_smem);

    void* cnt_ptr = nullptr;
    cudaGetSymbolAddress(&cnt_ptr, g_count);
    cudaMemsetAsync(cnt_ptr, 0, NB * sizeof(int));

    router_kernel<<<NTOK / 32, 256>>>(x, rw);
    expert_kernel<<<148, 512, ek_smem>>>(x, dw, uw, out);
}

// round 9
// speedup vs baseline: 2.3630x; 2.3630x over previous
#include <cuda_runtime.h>
#include <math.h>

// Problem constants
#define H    2048
#define E    8
#define I16  16
#define NTOK 8192
#define NB   64            // bucket ids lo*8+hi (28 valid)
#define TB   64            // tokens per tile
#define KC   128           // k-chunk (phase A)
#define NCH  (H / KC)      // 16
#define XP   132           // X/D row pitch (floats), mod 32 = 4
#define ASP  68            // Red/As pitch over tokens
#define UPB  260           // Us row pitch (floats), 256-h passes

// smem layout (float offsets); Us double-buffer reuses the XD region
#define XDSZ     (96 * XP)                 // one X+D buffer: 12672 floats
#define RED_OFF  (3 * XDSZ)                // 38016
#define AS_OFF   (RED_OFF + 8 * 32 * ASP)  // 38016 + 17408 = 55424
#define SM_FLOATS (AS_OFF + 32 * ASP)      // 57600 floats = 230400 B
#define USBUF    (32 * UPB)                // 8320 floats per Us buffer

// f32x2 packed-math helpers
#define FMA2(d, a, b) asm("fma.rn.f32x2 %0, %1, %2, %0;" : "+l"(d) : "l"(a), "l"(b))
#define PACK2(d, f)   asm("mov.b64 %0, {%1, %1};" : "=l"(d) : "f"(f))
#define UNPACK2(lo, hi, d) asm("mov.b64 {%0, %1}, %2;" : "=f"(lo), "=f"(hi) : "l"(d))

__device__ __forceinline__ unsigned su32(const void* p) {
    return (unsigned)__cvta_generic_to_shared(p);
}
#define CP16(dst, src) asm volatile("cp.async.cg.shared.global [%0], [%1], 16;" :: "r"(dst), "l"(src))
#define CP_COMMIT()    asm volatile("cp.async.commit_group;" ::: "memory")
#define CP_WAIT1()     asm volatile("cp.async.wait_group 1;" ::: "memory")
#define CP_WAIT0()     asm volatile("cp.async.wait_group 0;" ::: "memory")

// ---------------- device scratch ----------------
__device__ int    g_count[NB];
__device__ int    g_tok[NB][NTOK];
__device__ float2 g_gate[NB][NTOK];

// ---------------- K1: router (no smem; rw L1-resident; 4 tok/warp) ----
__global__ __launch_bounds__(256)
void router_kernel(const float* __restrict__ x,
                   const float* __restrict__ rw) {
    const int w = threadIdx.x >> 5;
    const int l = threadIdx.x & 31;
    const int t0 = blockIdx.x * 32 + w * 4;

    unsigned long long acc[E][4];
#pragma unroll
    for (int e = 0; e < E; e++)
#pragma unroll
        for (int j = 0; j < 4; j++) acc[e][j] = 0ull;

#pragma unroll 2
    for (int s = 0; s < 16; s++) {
        ulonglong2 xv[4];
#pragma unroll
        for (int j = 0; j < 4; j++)
            xv[j] = ((const ulonglong2*)(x + (size_t)(t0 + j) * H))[l + 32 * s];
#pragma unroll
        for (int e = 0; e < E; e++) {
            ulonglong2 wv = ((const ulonglong2*)(rw + e * H))[l + 32 * s];
#pragma unroll
            for (int j = 0; j < 4; j++) {
                FMA2(acc[e][j], xv[j].x, wv.x);
                FMA2(acc[e][j], xv[j].y, wv.y);
            }
        }
    }

    float lg[E];
#pragma unroll
    for (int e = 0; e < E; e++) {
#pragma unroll
        for (int j = 0; j < 4; j++) {
            float s0, s1;
            UNPACK2(s0, s1, acc[e][j]);
            float v = s0 + s1;
#pragma unroll
            for (int o = 16; o > 0; o >>= 1) v += __shfl_xor_sync(0xffffffffu, v, o);
            if (l == j) lg[e] = v;
        }
    }

    if (l < 4) {
        int t = t0 + l;
        float m = lg[0];
#pragma unroll
        for (int e = 1; e < E; e++) m = fmaxf(m, lg[e]);
        float wgt[E]; float ssum = 0.f;
#pragma unroll
        for (int e = 0; e < E; e++) { wgt[e] = __expf(lg[e] - m); ssum += wgt[e]; }
        float inv = 1.f / ssum;

        int i1 = 0; float v1 = wgt[0];
#pragma unroll
        for (int e = 1; e < E; e++) if (wgt[e] > v1) { v1 = wgt[e]; i1 = e; }
        int i2 = -1; float v2 = -1.f;
#pragma unroll
        for (int e = 0; e < E; e++)
            if (e != i1 && wgt[e] > v2) { v2 = wgt[e]; i2 = e; }

        float g1 = v1 * inv, g2 = v2 * inv;
        int lo, hi; float glo, ghi;
        if (i1 < i2) { lo = i1; hi = i2; glo = g1; ghi = g2; }
        else         { lo = i2; hi = i1; glo = g2; ghi = g1; }
        int p = lo * 8 + hi;
        int slot = atomicAdd(&g_count[p], 1);
        g_tok[p][slot]  = t;
        g_gate[p][slot] = make_float2(glo, ghi);
    }
}

// ---------------- K2: expert compute ----------------
// Phase A: C[64 tok][32 i] = X·D^T, split-K x8 (warp = 16k slice of KC=128
//   chunk), thread tile 8 tok x 8 i; depth-3 cp.async, 1 barrier/chunk.
// Phase B: out = A·U, 8 passes of 256 h; warp = 8 tokens, lane = 8 h;
//   Us double-buffered, coalesced LDG staging, 1 barrier/pass.
__global__ __launch_bounds__(256, 1)
void expert_kernel(const float* __restrict__ x,
                   const float* __restrict__ dw,
                   const float* __restrict__ uw,
                   float* __restrict__ out) {
    extern __shared__ float sm[];
    float* Red = sm + RED_OFF;
    float* As  = sm + AS_OFF;

    __shared__ int    pref[NB + 1];
    __shared__ int    Ts[TB];
    __shared__ float2 Gs[TB];

    const int tid = threadIdx.x;
    const int w = tid >> 5;          // warp = k-slice (A) / token group (B)
    const int l = tid & 31;
    const int tg = l & 7;            // phase A token interleave
    const int ig = l >> 3;           // phase A i interleave 0..3

    // flat tile prefix over buckets
    if (tid < NB) {
        int lo_ = tid >> 3, hi_ = tid & 7;
        pref[tid + 1] = (lo_ < hi_) ? (g_count[tid] + TB - 1) / TB : 0;
    }
    __syncthreads();
    if (tid == 0) {
        int s = 0;
        pref[0] = 0;
        for (int i = 1; i <= NB; i++) { s += pref[i]; pref[i] = s; }
    }
    __syncthreads();
    const int ntiles = pref[NB];

    for (int ft = blockIdx.x; ft < ntiles; ft += gridDim.x) {
        int a = 0, b = NB;
        while (b - a > 1) { int mM = (a + b) >> 1; if (pref[mM] <= ft) a = mM; else b = mM; }
        const int p  = a;
        const int lo = p >> 3, hi = p & 7;
        const int cnt  = g_count[p];
        const int base = (ft - pref[p]) * TB;
        const int n    = min(TB, cnt - base);

        __syncthreads();             // prev tile fully done with smem
        if (tid < TB) {
            int src = base + ((tid < n) ? tid : 0);
            Ts[tid] = g_tok[p][src];
            float2 gg = g_gate[p][src];
            if (tid >= n) gg = make_float2(0.f, 0.f);
            Gs[tid] = gg;
        }
        __syncthreads();

        // ================= Phase A =================
        unsigned long long accP[8][8];
#pragma unroll
        for (int u = 0; u < 8; u++)
#pragma unroll
            for (int v = 0; v < 8; v++) accP[u][v] = 0ull;

        auto stage = [&](int c, int bb) {
            float* dst = sm + bb * XDSZ;
            int koff = c * KC;
#pragma unroll
            for (int j = 0; j < 8; j++) {
                int idx = tid + 256 * j, r = idx >> 5, q = idx & 31;
                CP16(su32(dst + r * XP + 4 * q),
                     x + (size_t)Ts[r] * H + koff + 4 * q);
            }
#pragma unroll
            for (int j = 0; j < 4; j++) {
                int idx = tid + 256 * j, r = idx >> 5, q = idx & 31;
                int e = (r < 16) ? lo : hi;
                CP16(su32(dst + (64 + r) * XP + 4 * q),
                     dw + (size_t)(e * I16 + (r & 15)) * H + koff + 4 * q);
            }
        };

        stage(0, 0); CP_COMMIT();
        stage(1, 1); CP_COMMIT();

        int buf = 0;
        for (int c = 0; c < NCH; c++) {
            if (c == NCH - 1) { CP_WAIT0(); } else { CP_WAIT1(); }
            __syncthreads();         // buf c visible; buf (c+2)%3 free
            if (c + 2 < NCH) { stage(c + 2, (c + 2) % 3); CP_COMMIT(); }

            const ulonglong2* B4 = (const ulonglong2*)(sm + buf * XDSZ);
#pragma unroll
            for (int q2 = 0; q2 < 4; q2++) {
                const int kq = (w << 2) + q2;
                ulonglong2 xv[8];
#pragma unroll
                for (int u = 0; u < 8; u++)
                    xv[u] = B4[(tg + 8 * u) * 33 + kq];
#pragma unroll
                for (int v = 0; v < 8; v++) {
                    ulonglong2 dv = B4[(64 + ig + 4 * v) * 33 + kq];
#pragma unroll
                    for (int u = 0; u < 8; u++) {
                        FMA2(accP[u][v], xv[u].x, dv.x);
                        FMA2(accP[u][v], xv[u].y, dv.y);
                    }
                }
            }
            buf = (buf == 2) ? 0 : buf + 1;
        }

        // split-K partials -> Red[w][i][t]
#pragma unroll
        for (int u = 0; u < 8; u++)
#pragma unroll
            for (int v = 0; v < 8; v++) {
                float s0, s1;
                UNPACK2(s0, s1, accP[u][v]);
                Red[w * (32 * ASP) + (ig + 4 * v) * ASP + (tg + 8 * u)] = s0 + s1;
            }
        __syncthreads();

        // issue pass-0 U loads (overlap with reduce)
        float4 ub[8];
#pragma unroll
        for (int j = 0; j < 8; j++) {
            int idx = j * 256 + tid;
            int iq = idx & 3, h = (idx >> 2) & 255, e2 = idx >> 10;
            int eg = e2 ? hi : lo;
            ub[j] = *(const float4*)(uw + ((size_t)eg * H + h) * I16 + 4 * iq);
        }

        // reduce + silu + gate -> As[i][t]
#pragma unroll
        for (int j = 0; j < 8; j++) {
            int idx = j * 256 + tid;
            int i = idx >> 6, t = idx & 63;
            float hv = 0.f;
#pragma unroll
            for (int kk = 0; kk < 8; kk++)
                hv += Red[kk * (32 * ASP) + i * ASP + t];
            float2 gg = Gs[t];
            float gate = (i < 16) ? gg.x : gg.y;
            float sig = 1.f / (1.f + __expf(-hv));
            As[i * ASP + t] = gate * hv * sig;
        }
        __syncthreads();             // As ready; XD region free for Us bufs

        // ================= Phase B =================
        // 8 passes of 256 h; Us ping-pong at sm[0] / sm[USBUF].
        for (int pass = 0; pass < 8; pass++) {
            float* Ub = sm + (pass & 1) * USBUF;
            // STS staged pass (regs -> smem)
#pragma unroll
            for (int j = 0; j < 8; j++) {
                int idx = j * 256 + tid;
                int iq = idx & 3, h = (idx >> 2) & 255, e2 = idx >> 10;
                int rb = e2 * 16 + 4 * iq;
                Ub[(rb + 0) * UPB + h] = ub[j].x;
                Ub[(rb + 1) * UPB + h] = ub[j].y;
                Ub[(rb + 2) * UPB + h] = ub[j].z;
                Ub[(rb + 3) * UPB + h] = ub[j].w;
            }
            __syncthreads();         // Us pass visible (single barrier per pass)

            // prefetch next pass U into regs
            if (pass + 1 < 8) {
#pragma unroll
                for (int j = 0; j < 8; j++) {
                    int idx = j * 256 + tid;
                    int iq = idx & 3, h = (idx >> 2) & 255, e2 = idx >> 10;
                    int eg = e2 ? hi : lo;
                    ub[j] = *(const float4*)(uw + ((size_t)eg * H + (pass + 1) * 256 + h) * I16 + 4 * iq);
                }
            }

            // compute: warp = 8 tokens, lane = 8 h (4l + 128m)
            ulonglong2 acc2[8][2];
#pragma unroll
            for (int j = 0; j < 8; j++)
#pragma unroll
                for (int m = 0; m < 2; m++) { acc2[j][m].x = 0ull; acc2[j][m].y = 0ull; }

#pragma unroll 4
            for (int k = 0; k < 32; k++) {
                float4 aA = *(const float4*)(As + k * ASP + w * 8);
                float4 aB = *(const float4*)(As + k * ASP + w * 8 + 4);
                unsigned long long ap[8];
                PACK2(ap[0], aA.x); PACK2(ap[1], aA.y);
                PACK2(ap[2], aA.z); PACK2(ap[3], aA.w);
                PACK2(ap[4], aB.x); PACK2(ap[5], aB.y);
                PACK2(ap[6], aB.z); PACK2(ap[7], aB.w);
#pragma unroll
                for (int m = 0; m < 2; m++) {
                    ulonglong2 uv = *(const ulonglong2*)(Ub + k * UPB + 4 * l + 128 * m);
#pragma unroll
                    for (int j = 0; j < 8; j++) {
                        FMA2(acc2[j][m].x, ap[j], uv.x);
                        FMA2(acc2[j][m].y, ap[j], uv.y);
                    }
                }
            }

#pragma unroll
            for (int j = 0; j < 8; j++) {
                int tl = w * 8 + j;
                if (tl < n) {
                    float* orow = out + (size_t)Ts[tl] * H + pass * 256 + 4 * l;
#pragma unroll
                    for (int m = 0; m < 2; m++) {
                        float4 ov;
                        UNPACK2(ov.x, ov.y, acc2[j][m].x);
                        UNPACK2(ov.z, ov.w, acc2[j][m].y);
                        *(float4*)(orow + 128 * m) = ov;
                    }
                }
            }
            // no barrier here: next pass STS targets the other Us buffer,
            // and the barrier inside the next iteration protects reuse.
        }
        __syncthreads();             // tile done before Ts/Gs/As overwritten
    }
}

// ---------------- launch ----------------
extern "C" void kernel_launch(void* const* d_in, const int* in_sizes, int n_in,
                              void* d_out, int out_size) {
    const float* x  = (const float*)d_in[0];
    const float* rw = (const float*)d_in[1];
    const float* dw = (const float*)d_in[2];
    const float* uw = (const float*)d_in[3];
    float* out = (float*)d_out;

    const int ek_smem = SM_FLOATS * sizeof(float); // 230400 B
    cudaFuncSetAttribute(expert_kernel, cudaFuncAttributeMaxDynamicSharedMemorySize, ek_smem);

    void* cnt_ptr = nullptr;
    cudaGetSymbolAddress(&cnt_ptr, g_count);
    cudaMemsetAsync(cnt_ptr, 0, NB * sizeof(int));

    router_kernel<<<NTOK / 32, 256>>>(x, rw);
    expert_kernel<<<148, 256, ek_smem>>>(x, dw, uw, out);
}

// round 10
// speedup vs baseline: 3.1253x; 1.3226x over previous
#include <cuda_runtime.h>
#include <math.h>
#include <stdint.h>

// Problem constants
#define H    2048
#define E    8
#define I16  16
#define NTOK 8192
#define NB   64            // bucket ids lo*8+hi (28 valid)
#define TB   64            // tokens per tile
#define KC   128           // k-chunk (phase A)
#define NCH  (H / KC)      // 16
#define XP   132           // X/D row pitch (floats)
#define AIP  36            // As pitch over i
#define UPB  264           // Uc row pitch (floats)

// smem layout (float offsets)
#define XDSZ   (96 * XP)               // one X+D buffer: 12672 floats
#define USZ    (32 * UPB)              // one Uc buffer: 8448 floats (overlaps XD region)
#define AS_OFF (2 * XDSZ)              // 25344
#define SM_FLOATS (AS_OFF + TB * AIP)  // 27648 floats = 110592 B

// f32x2 helpers (router)
#define FMA2(d, a, b) asm("fma.rn.f32x2 %0, %1, %2, %0;" : "+l"(d) : "l"(a), "l"(b))
#define UNPACK2(lo, hi, d) asm("mov.b64 {%0, %1}, %2;" : "=f"(lo), "=f"(hi) : "l"(d))

__device__ __forceinline__ unsigned su32(const void* p) {
    return (unsigned)__cvta_generic_to_shared(p);
}
#define CP16(dst, src) asm volatile("cp.async.cg.shared.global [%0], [%1], 16;" :: "r"(dst), "l"(src))
#define CP_COMMIT()    asm volatile("cp.async.commit_group;" ::: "memory")
#define CP_WAIT0()     asm volatile("cp.async.wait_group 0;" ::: "memory")

__device__ __forceinline__ uint32_t cvt_tf32(float f) {
    uint32_t r;
    asm("cvt.rna.tf32.f32 %0, %1;" : "=r"(r) : "f"(f));
    return r;
}

__device__ __forceinline__ void mma_tf32(float d[4],
                                         uint32_t a0, uint32_t a1, uint32_t a2, uint32_t a3,
                                         uint32_t b0, uint32_t b1) {
    asm volatile(
        "mma.sync.aligned.m16n8k8.row.col.f32.tf32.tf32.f32 "
        "{%0,%1,%2,%3}, {%4,%5,%6,%7}, {%8,%9}, {%0,%1,%2,%3};"
        : "+f"(d[0]), "+f"(d[1]), "+f"(d[2]), "+f"(d[3])
        : "r"(a0), "r"(a1), "r"(a2), "r"(a3), "r"(b0), "r"(b1));
}

// ---------------- device scratch ----------------
__device__ int      g_count[NB];
__device__ int      g_tok[NB][NTOK];
__device__ float2   g_gate[NB][NTOK];
__device__ float    g_dwc[E * I16 * H];   // dw, tf32-rounded, same layout [e][i][h]
__device__ float    g_ut[E * I16 * H];    // uw transposed+rounded: [e][i][h]

// ---------------- K0: prep — round dw, transpose+round uw ----------------
__global__ __launch_bounds__(256)
void prep_kernel(const float* __restrict__ dw, const float* __restrict__ uw) {
    int tid = blockIdx.x * 256 + threadIdx.x;        // 65536 threads, 1 float4 each
    // dwc (layout preserved)
    float4 v = ((const float4*)dw)[tid];
    float4 o;
    *(uint32_t*)&o.x = cvt_tf32(v.x);
    *(uint32_t*)&o.y = cvt_tf32(v.y);
    *(uint32_t*)&o.z = cvt_tf32(v.z);
    *(uint32_t*)&o.w = cvt_tf32(v.w);
    ((float4*)g_dwc)[tid] = o;
    // ut: src uw[e][h][i] (float4 = 4 consecutive i) -> g_ut[e][i][h]
    float4 u = ((const float4*)uw)[tid];
    int e  = tid >> 13;            // H*I16/4 = 8192 float4 per expert
    int rm = tid & 8191;
    int h  = rm >> 2;
    int iq = (rm & 3) * 4;
    uint32_t* utb = (uint32_t*)(g_ut + (size_t)(e * I16) * H + h);
    utb[(iq + 0) * H] = cvt_tf32(u.x);
    utb[(iq + 1) * H] = cvt_tf32(u.y);
    utb[(iq + 2) * H] = cvt_tf32(u.z);
    utb[(iq + 3) * H] = cvt_tf32(u.w);
}

// ---------------- K1: router (fp32 f32x2, 4 tok/warp) ----------------
__global__ __launch_bounds__(256)
void router_kernel(const float* __restrict__ x,
                   const float* __restrict__ rw) {
    const int w = threadIdx.x >> 5;
    const int l = threadIdx.x & 31;
    const int t0 = blockIdx.x * 32 + w * 4;

    unsigned long long acc[E][4];
#pragma unroll
    for (int e = 0; e < E; e++)
#pragma unroll
        for (int j = 0; j < 4; j++) acc[e][j] = 0ull;

#pragma unroll 2
    for (int s = 0; s < 16; s++) {
        ulonglong2 xv[4];
#pragma unroll
        for (int j = 0; j < 4; j++)
            xv[j] = ((const ulonglong2*)(x + (size_t)(t0 + j) * H))[l + 32 * s];
#pragma unroll
        for (int e = 0; e < E; e++) {
            ulonglong2 wv = ((const ulonglong2*)(rw + e * H))[l + 32 * s];
#pragma unroll
            for (int j = 0; j < 4; j++) {
                FMA2(acc[e][j], xv[j].x, wv.x);
                FMA2(acc[e][j], xv[j].y, wv.y);
            }
        }
    }

    float lg[E];
#pragma unroll
    for (int e = 0; e < E; e++) {
#pragma unroll
        for (int j = 0; j < 4; j++) {
            float s0, s1;
            UNPACK2(s0, s1, acc[e][j]);
            float v = s0 + s1;
#pragma unroll
            for (int o = 16; o > 0; o >>= 1) v += __shfl_xor_sync(0xffffffffu, v, o);
            if (l == j) lg[e] = v;
        }
    }

    if (l < 4) {
        int t = t0 + l;
        float m = lg[0];
#pragma unroll
        for (int e = 1; e < E; e++) m = fmaxf(m, lg[e]);
        float wgt[E]; float ssum = 0.f;
#pragma unroll
        for (int e = 0; e < E; e++) { wgt[e] = __expf(lg[e] - m); ssum += wgt[e]; }
        float inv = 1.f / ssum;

        int i1 = 0; float v1 = wgt[0];
#pragma unroll
        for (int e = 1; e < E; e++) if (wgt[e] > v1) { v1 = wgt[e]; i1 = e; }
        int i2 = -1; float v2 = -1.f;
#pragma unroll
        for (int e = 0; e < E; e++)
            if (e != i1 && wgt[e] > v2) { v2 = wgt[e]; i2 = e; }

        float g1 = v1 * inv, g2 = v2 * inv;
        int lo, hi; float glo, ghi;
        if (i1 < i2) { lo = i1; hi = i2; glo = g1; ghi = g2; }
        else         { lo = i2; hi = i1; glo = g2; ghi = g1; }
        int p = lo * 8 + hi;
        int slot = atomicAdd(&g_count[p], 1);
        g_tok[p][slot]  = t;
        g_gate[p][slot] = make_float2(glo, ghi);
    }
}

// ---------------- K2: expert compute, tf32 tensor cores ----------------
// Phase A: C[64,32] = X[64,2048]·D[32,2048]^T. Warp = 16 tok x 16 i,
//   full K, mma.m16n8k8.tf32; X/D chunks cp.async double-buffered.
// Phase B: out[64,2048] = As[64,32]·Ut[32,2048]; Uc[32][256] per pass,
//   double-buffered; d regs stored directly to gmem.
__global__ __launch_bounds__(256, 1)
void expert_kernel(const float* __restrict__ x,
                   float* __restrict__ out) {
    extern __shared__ float sm[];
    float* As = sm + AS_OFF;

    __shared__ int    pref[NB + 1];
    __shared__ int    Ts[TB];
    __shared__ float2 Gs[TB];

    const int tid = threadIdx.x;
    const int w = tid >> 5;
    const int l = tid & 31;
    const int gp  = l >> 2;          // group id (0..7)
    const int tg4 = l & 3;           // thread in group
    // phase A warp tile
    const int mw = w & 3;            // token block (16 tok)
    const int nw = w >> 2;           // i block (16 i)
    // phase B warp tile
    const int m2 = w & 3;            // token block
    const int nh = w >> 2;           // h half within pass (128 h)

    // flat tile prefix
    if (tid < NB) {
        int lo_ = tid >> 3, hi_ = tid & 7;
        pref[tid + 1] = (lo_ < hi_) ? (g_count[tid] + TB - 1) / TB : 0;
    }
    __syncthreads();
    if (tid == 0) {
        int s = 0;
        pref[0] = 0;
        for (int i = 1; i <= NB; i++) { s += pref[i]; pref[i] = s; }
    }
    __syncthreads();
    const int ntiles = pref[NB];

    for (int ft = blockIdx.x; ft < ntiles; ft += gridDim.x) {
        int a = 0, b = NB;
        while (b - a > 1) { int mM = (a + b) >> 1; if (pref[mM] <= ft) a = mM; else b = mM; }
        const int p  = a;
        const int lo = p >> 3, hi = p & 7;
        const int cnt  = g_count[p];
        const int base = (ft - pref[p]) * TB;
        const int n    = min(TB, cnt - base);

        __syncthreads();             // prev tile fully done with smem
        if (tid < TB) {
            int src = base + ((tid < n) ? tid : 0);
            Ts[tid] = g_tok[p][src];
            float2 gg = g_gate[p][src];
            if (tid >= n) gg = make_float2(0.f, 0.f);
            Gs[tid] = gg;
        }
        __syncthreads();

        // ================= Phase A =================
        float d[2][4];
#pragma unroll
        for (int t = 0; t < 2; t++)
#pragma unroll
            for (int q = 0; q < 4; q++) d[t][q] = 0.f;

        auto stage = [&](int c, int bb) {
            float* dst = sm + bb * XDSZ;
            int koff = c * KC;
#pragma unroll
            for (int j = 0; j < 8; j++) {
                int idx = tid + 256 * j, r = idx >> 5, q = idx & 31;
                CP16(su32(dst + r * XP + 4 * q),
                     x + (size_t)Ts[r] * H + koff + 4 * q);
            }
#pragma unroll
            for (int j = 0; j < 4; j++) {
                int idx = tid + 256 * j, r = idx >> 5, q = idx & 31;
                int e = (r < 16) ? lo : hi;
                CP16(su32(dst + (64 + r) * XP + 4 * q),
                     g_dwc + (size_t)(e * I16 + (r & 15)) * H + koff + 4 * q);
            }
        };

        stage(0, 0); CP_COMMIT();

        const int xr0 = (16 * mw + gp) * XP;
        const int xr1 = xr0 + 8 * XP;
        const int dr0 = (64 + 16 * nw + gp) * XP;      // D rows live at +64
        const int dr1 = dr0 + 8 * XP;

        for (int c = 0; c < NCH; c++) {
            CP_WAIT0();
            __syncthreads();         // chunk c visible; buf (c+1)&1 free
            if (c + 1 < NCH) { stage(c + 1, (c + 1) & 1); CP_COMMIT(); }

            const float*    Xb = sm + (c & 1) * XDSZ;
            const uint32_t* Db = (const uint32_t*)Xb;
#pragma unroll
            for (int s = 0; s < 16; s++) {
                const int ca = 8 * s + tg4;
                uint32_t a0 = cvt_tf32(Xb[xr0 + ca]);
                uint32_t a1 = cvt_tf32(Xb[xr1 + ca]);
                uint32_t a2 = cvt_tf32(Xb[xr0 + ca + 4]);
                uint32_t a3 = cvt_tf32(Xb[xr1 + ca + 4]);
                uint32_t b00 = Db[dr0 + ca];
                uint32_t b01 = Db[dr0 + ca + 4];
                uint32_t b10 = Db[dr1 + ca];
                uint32_t b11 = Db[dr1 + ca + 4];
                mma_tf32(d[0], a0, a1, a2, a3, b00, b01);
                mma_tf32(d[1], a0, a1, a2, a3, b10, b11);
            }
        }

        // epilogue: silu + gate + tf32-round -> As[tok][i]
        {
            int r0 = 16 * mw + gp, r1 = r0 + 8;
            float2 gg0 = Gs[r0], gg1 = Gs[r1];
            float gt0 = nw ? gg0.y : gg0.x;
            float gt1 = nw ? gg1.y : gg1.x;
#pragma unroll
            for (int t = 0; t < 2; t++) {
                int cbase = 16 * nw + 8 * t + 2 * tg4;
#pragma unroll
                for (int q = 0; q < 4; q++) {
                    float hv = d[t][q];
                    float sig = 1.f / (1.f + __expf(-hv));
                    float gate = (q < 2) ? gt0 : gt1;
                    float val = gate * hv * sig;
                    int row = (q < 2) ? r0 : r1;
                    int col = cbase + (q & 1);
                    *(uint32_t*)&As[row * AIP + col] = cvt_tf32(val);
                }
            }
        }
        __syncthreads();             // As ready; XD region free for Uc

        // ================= Phase B =================
        auto stage_u = [&](int pp, int bb) {
            float* dst = sm + bb * USZ;
#pragma unroll
            for (int j = 0; j < 8; j++) {
                int idx = tid + 256 * j, r = idx >> 6, q = idx & 63;
                int e = (r < 16) ? lo : hi;
                CP16(su32(dst + r * UPB + 4 * q),
                     g_ut + (size_t)(e * I16 + (r & 15)) * H + pp * 256 + 4 * q);
            }
        };

        stage_u(0, 0); CP_COMMIT();

        // hoist A fragments (constant across passes) and out pointers
        uint32_t pa[4][4];
        {
            const uint32_t* Au = (const uint32_t*)As;
            int r0 = (16 * m2 + gp) * AIP, r1 = r0 + 8 * AIP;
#pragma unroll
            for (int ks = 0; ks < 4; ks++) {
                int cb = 8 * ks + tg4;
                pa[ks][0] = Au[r0 + cb];
                pa[ks][1] = Au[r1 + cb];
                pa[ks][2] = Au[r0 + cb + 4];
                pa[ks][3] = Au[r1 + cb + 4];
            }
        }
        const int tr0 = 16 * m2 + gp, tr1 = tr0 + 8;
        const bool v0 = tr0 < n, v1 = tr1 < n;
        float* o0 = out + (size_t)Ts[tr0] * H;
        float* o1 = out + (size_t)Ts[tr1] * H;

        for (int pass = 0; pass < 8; pass++) {
            CP_WAIT0();
            __syncthreads();         // Uc pass visible; other buffer free
            if (pass + 1 < 8) { stage_u(pass + 1, (pass + 1) & 1); CP_COMMIT(); }

            const uint32_t* Ub = (const uint32_t*)(sm + (pass & 1) * USZ);
            const int hw = 128 * nh;
#pragma unroll 4
            for (int j = 0; j < 16; j++) {
                const int hbb = hw + 8 * j;
                float dd[4] = {0.f, 0.f, 0.f, 0.f};
#pragma unroll
                for (int ks = 0; ks < 4; ks++) {
                    uint32_t b0 = Ub[(8 * ks + tg4) * UPB + hbb + gp];
                    uint32_t b1 = Ub[(8 * ks + tg4 + 4) * UPB + hbb + gp];
                    mma_tf32(dd, pa[ks][0], pa[ks][1], pa[ks][2], pa[ks][3], b0, b1);
                }
                int h0 = pass * 256 + hbb + 2 * tg4;
                if (v0) *(float2*)(o0 + h0) = make_float2(dd[0], dd[1]);
                if (v1) *(float2*)(o1 + h0) = make_float2(dd[2], dd[3]);
            }
        }
    }
}

// ---------------- launch ----------------
extern "C" void kernel_launch(void* const* d_in, const int* in_sizes, int n_in,
                              void* d_out, int out_size) {
    const float* x  = (const float*)d_in[0];
    const float* rw = (const float*)d_in[1];
    const float* dw = (const float*)d_in[2];
    const float* uw = (const float*)d_in[3];
    float* out = (float*)d_out;

    const int ek_smem = SM_FLOATS * sizeof(float); // 110592 B
    cudaFuncSetAttribute(expert_kernel, cudaFuncAttributeMaxDynamicSharedMemorySize, ek_smem);

    void* cnt_ptr = nullptr;
    cudaGetSymbolAddress(&cnt_ptr, g_count);
    cudaMemsetAsync(cnt_ptr, 0, NB * sizeof(int));

    prep_kernel<<<256, 256>>>(dw, uw);
    router_kernel<<<NTOK / 32, 256>>>(x, rw);
    expert_kernel<<<148, 256, ek_smem>>>(x, out);
}